// round 1
// baseline (speedup 1.0000x reference)
#include <cuda_runtime.h>
#include <cuda_bf16.h>
#include <math.h>

// Problem constants
#define NQ     131072
#define LCH    128
#define HH     64
#define WW     64
#define K1     131      // 128 feats + 3 raw query
#define K1P    136      // padded to multiple of 8
#define HID    512

// ---------------------------------------------------------------------------
// Scratch (no cudaMalloc allowed -> device globals)
// ---------------------------------------------------------------------------
__device__ float g_h0[(size_t)NQ * K1P];     // sampled feats + query, padded
__device__ float g_w1[(size_t)K1P * HID];    // W1 zero-padded to 136 rows
__device__ float g_a [(size_t)NQ * HID];     // ping
__device__ float g_b [(size_t)NQ * HID];     // pong

// ---------------------------------------------------------------------------
// Pad W1 (131x512) -> g_w1 (136x512), zero rows 131..135
// ---------------------------------------------------------------------------
__global__ void pad_w1_kernel(const float* __restrict__ W1, float* __restrict__ out) {
    int i = blockIdx.x * blockDim.x + threadIdx.x;
    if (i < K1P * HID) {
        int k = i / HID, n = i % HID;
        out[i] = (k < K1) ? W1[k * HID + n] : 0.0f;
    }
}

// ---------------------------------------------------------------------------
// Triplanar bilinear sampler: one thread per query.
// planes: (3*128, 64, 64) channel-major. Writes h0[n*136 + c].
// ---------------------------------------------------------------------------
__global__ void sampler_kernel(const float* __restrict__ planes,
                               const float* __restrict__ query,
                               float* __restrict__ h0) {
    int n = blockIdx.x * blockDim.x + threadIdx.x;
    if (n >= NQ) return;

    float q0 = query[3 * n + 0];
    float q1 = query[3 * n + 1];
    float q2 = query[3 * n + 2];

    // q / (1 + PAD)
    float u[3], v[3];
    u[0] = q0 / 1.1f; v[0] = q2 / 1.1f;   // xz plane
    u[1] = q1 / 1.1f; v[1] = q2 / 1.1f;   // yz plane
    u[2] = q0 / 1.1f; v[2] = q1 / 1.1f;   // xy plane

    int   idx00[3], idx01[3], idx10[3], idx11[3];
    float w00[3], w01[3], w10[3], w11[3];

    #pragma unroll
    for (int p = 0; p < 3; ++p) {
        float x = (u[p] + 1.0f) * 0.5f * (WW - 1);
        float y = (v[p] + 1.0f) * 0.5f * (HH - 1);
        float x0f = floorf(x);
        float y0f = floorf(y);
        float wx = x - x0f;
        float wy = y - y0f;
        int x0 = (int)x0f; x0 = min(max(x0, 0), WW - 1);
        int y0 = (int)y0f; y0 = min(max(y0, 0), HH - 1);
        int x1 = min(x0 + 1, WW - 1);
        int y1 = min(y0 + 1, HH - 1);
        idx00[p] = y0 * WW + x0;
        idx01[p] = y0 * WW + x1;
        idx10[p] = y1 * WW + x0;
        idx11[p] = y1 * WW + x1;
        w00[p] = (1.0f - wx) * (1.0f - wy);
        w01[p] = wx * (1.0f - wy);
        w10[p] = (1.0f - wx) * wy;
        w11[p] = wx * wy;
    }

    const float* P0 = planes;
    const float* P1 = planes + (size_t)LCH * HH * WW;
    const float* P2 = planes + (size_t)2 * LCH * HH * WW;

    float* __restrict__ dst = h0 + (size_t)n * K1P;

    #pragma unroll 4
    for (int c = 0; c < LCH; ++c) {
        const float* f0 = P0 + (size_t)c * (HH * WW);
        const float* f1 = P1 + (size_t)c * (HH * WW);
        const float* f2 = P2 + (size_t)c * (HH * WW);
        float s;
        s  = w00[0] * __ldg(f0 + idx00[0]) + w01[0] * __ldg(f0 + idx01[0])
           + w10[0] * __ldg(f0 + idx10[0]) + w11[0] * __ldg(f0 + idx11[0]);
        s += w00[1] * __ldg(f1 + idx00[1]) + w01[1] * __ldg(f1 + idx01[1])
           + w10[1] * __ldg(f1 + idx10[1]) + w11[1] * __ldg(f1 + idx11[1]);
        s += w00[2] * __ldg(f2 + idx00[2]) + w01[2] * __ldg(f2 + idx01[2])
           + w10[2] * __ldg(f2 + idx10[2]) + w11[2] * __ldg(f2 + idx11[2]);
        dst[c] = s;
    }
    dst[128] = q0;
    dst[129] = q1;
    dst[130] = q2;
    dst[131] = 0.0f;
    dst[132] = 0.0f;
    dst[133] = 0.0f;
    dst[134] = 0.0f;
    dst[135] = 0.0f;
}

// ---------------------------------------------------------------------------
// SGEMM + bias + ReLU:  C[M x 512] = relu(A[M x K] * B[K x 512] + bias)
// BM=BN=128, BK=8, 256 threads, 8x8 microtile. lda passed in; ldb=ldc=512.
// M, N multiples of 128; K multiple of 8.
// ---------------------------------------------------------------------------
__global__ __launch_bounds__(256)
void sgemm_relu_kernel(const float* __restrict__ A, int lda,
                       const float* __restrict__ B,
                       const float* __restrict__ bias,
                       float* __restrict__ C,
                       int K) {
    __shared__ float As[8][128];
    __shared__ float Bs[8][128];

    const int tid = threadIdx.x;
    const int m0 = blockIdx.y * 128;
    const int n0 = blockIdx.x * 128;

    // A tile load mapping: 128 rows x 8 cols; 2 float4 per row
    const int arow = tid >> 1;          // 0..127
    const int aseg = (tid & 1) * 4;     // 0 or 4
    // B tile load mapping: 8 rows x 128 cols; 32 float4 per row
    const int brow = tid >> 5;          // 0..7
    const int bcol = (tid & 31) * 4;    // 0..124

    const int rm = (tid >> 4) * 8;      // 0..120
    const int rn = (tid & 15) * 8;      // 0..120

    float acc[8][8];
    #pragma unroll
    for (int i = 0; i < 8; ++i)
        #pragma unroll
        for (int j = 0; j < 8; ++j)
            acc[i][j] = 0.0f;

    for (int kt = 0; kt < K; kt += 8) {
        float4 av = *(const float4*)(A + (size_t)(m0 + arow) * lda + kt + aseg);
        As[aseg + 0][arow] = av.x;
        As[aseg + 1][arow] = av.y;
        As[aseg + 2][arow] = av.z;
        As[aseg + 3][arow] = av.w;
        float4 bv = *(const float4*)(B + (size_t)(kt + brow) * HID + n0 + bcol);
        *(float4*)(&Bs[brow][bcol]) = bv;
        __syncthreads();

        #pragma unroll
        for (int k = 0; k < 8; ++k) {
            float af[8], bf[8];
            #pragma unroll
            for (int i = 0; i < 8; ++i) af[i] = As[k][rm + i];
            #pragma unroll
            for (int j = 0; j < 8; ++j) bf[j] = Bs[k][rn + j];
            #pragma unroll
            for (int i = 0; i < 8; ++i)
                #pragma unroll
                for (int j = 0; j < 8; ++j)
                    acc[i][j] += af[i] * bf[j];
        }
        __syncthreads();
    }

    float bv[8];
    #pragma unroll
    for (int j = 0; j < 8; ++j) bv[j] = bias[n0 + rn + j];

    #pragma unroll
    for (int i = 0; i < 8; ++i) {
        float* crow = C + (size_t)(m0 + rm + i) * HID + n0 + rn;
        float4 o0, o1;
        o0.x = fmaxf(acc[i][0] + bv[0], 0.0f);
        o0.y = fmaxf(acc[i][1] + bv[1], 0.0f);
        o0.z = fmaxf(acc[i][2] + bv[2], 0.0f);
        o0.w = fmaxf(acc[i][3] + bv[3], 0.0f);
        o1.x = fmaxf(acc[i][4] + bv[4], 0.0f);
        o1.y = fmaxf(acc[i][5] + bv[5], 0.0f);
        o1.z = fmaxf(acc[i][6] + bv[6], 0.0f);
        o1.w = fmaxf(acc[i][7] + bv[7], 0.0f);
        *(float4*)(crow + 0) = o0;
        *(float4*)(crow + 4) = o1;
    }
}

// ---------------------------------------------------------------------------
// Head layer: out[n] = tanh(dot(H[n,:512], Wo) + bo). Warp per row.
// ---------------------------------------------------------------------------
__global__ void head_kernel(const float* __restrict__ H,
                            const float* __restrict__ Wo,
                            const float* __restrict__ bo,
                            float* __restrict__ out) {
    __shared__ float sW[HID];
    int tid = threadIdx.x;
    for (int i = tid; i < HID; i += blockDim.x) sW[i] = Wo[i];
    __syncthreads();

    int gwarp = (blockIdx.x * blockDim.x + tid) >> 5;
    int lane = tid & 31;
    if (gwarp >= NQ) return;

    const float* row = H + (size_t)gwarp * HID;
    float s = 0.0f;
    #pragma unroll
    for (int k = lane; k < HID; k += 32) s += row[k] * sW[k];
    #pragma unroll
    for (int o = 16; o > 0; o >>= 1) s += __shfl_xor_sync(0xFFFFFFFFu, s, o);
    if (lane == 0) out[gwarp] = tanhf(s + bo[0]);
}

// ---------------------------------------------------------------------------
// Launcher
// ---------------------------------------------------------------------------
extern "C" void kernel_launch(void* const* d_in, const int* in_sizes, int n_in,
                              void* d_out, int out_size) {
    const float* planes = (const float*)d_in[0];
    const float* query  = (const float*)d_in[1];
    const float* W1     = (const float*)d_in[2];
    const float* b1     = (const float*)d_in[3];
    const float* W2     = (const float*)d_in[4];
    const float* b2     = (const float*)d_in[5];
    const float* W3     = (const float*)d_in[6];
    const float* b3     = (const float*)d_in[7];
    const float* Wo     = (const float*)d_in[8];
    const float* bo     = (const float*)d_in[9];
    float* out = (float*)d_out;

    float *h0, *w1p, *A, *B;
    cudaGetSymbolAddress((void**)&h0,  g_h0);
    cudaGetSymbolAddress((void**)&w1p, g_w1);
    cudaGetSymbolAddress((void**)&A,   g_a);
    cudaGetSymbolAddress((void**)&B,   g_b);

    // 1. pad W1
    pad_w1_kernel<<<(K1P * HID + 255) / 256, 256>>>(W1, w1p);

    // 2. triplanar sampling -> h0 [NQ x 136]
    sampler_kernel<<<NQ / 256, 256>>>(planes, query, h0);

    dim3 gblk(HID / 128, NQ / 128);

    // 3. layer 1: h0[NQ x 136] x w1p[136 x 512] -> A
    sgemm_relu_kernel<<<gblk, 256>>>(h0, K1P, w1p, b1, A, K1P);

    // 4. layer 2: A x W2 -> B
    sgemm_relu_kernel<<<gblk, 256>>>(A, HID, W2, b2, B, HID);

    // 5. layer 3: B x W3 -> A
    sgemm_relu_kernel<<<gblk, 256>>>(B, HID, W3, b3, A, HID);

    // 6. head: tanh(A @ Wo + bo)
    head_kernel<<<(NQ * 32) / 256, 256>>>(A, Wo, bo, out);
}

// round 3
// speedup vs baseline: 2.3246x; 2.3246x over previous
#include <cuda_runtime.h>
#include <cuda_bf16.h>
#include <math.h>
#include <cstdint>

// ---------------------------------------------------------------------------
// Problem constants
// ---------------------------------------------------------------------------
#define NQ     131072
#define K1P    192        // 128 feats + 3 query + pad
#define HID    512

// ---------------------------------------------------------------------------
// Scratch (device globals; no cudaMalloc allowed)
// ---------------------------------------------------------------------------
__device__ float         g_planesT[3u * 64 * 64 * 128];
__device__ __nv_bfloat16 g_h0h[(size_t)NQ * K1P];
__device__ __nv_bfloat16 g_h0l[(size_t)NQ * K1P];
__device__ __nv_bfloat16 g_w1h[(size_t)HID * K1P], g_w1l[(size_t)HID * K1P];
__device__ __nv_bfloat16 g_w2h[(size_t)HID * HID], g_w2l[(size_t)HID * HID];
__device__ __nv_bfloat16 g_w3h[(size_t)HID * HID], g_w3l[(size_t)HID * HID];
__device__ __nv_bfloat16 g_ah[(size_t)NQ * HID], g_al[(size_t)NQ * HID];
__device__ __nv_bfloat16 g_bh[(size_t)NQ * HID], g_bl[(size_t)NQ * HID];

__device__ __forceinline__ void split_bf16(float x, __nv_bfloat16& h, __nv_bfloat16& l) {
    h = __float2bfloat16(x);
    l = __float2bfloat16(x - __bfloat162float(h));
}

__device__ __forceinline__ uint32_t smem_u32(const void* p) {
    uint32_t a;
    asm("{ .reg .u64 t; cvta.to.shared.u64 t, %1; cvt.u32.u64 %0, t; }" : "=r"(a) : "l"(p));
    return a;
}
__device__ __forceinline__ void cp16(uint32_t saddr, const void* g) {
    asm volatile("cp.async.cg.shared.global [%0], [%1], 16;" :: "r"(saddr), "l"(g));
}
__device__ __forceinline__ void ldsm4(uint32_t& r0, uint32_t& r1, uint32_t& r2, uint32_t& r3,
                                      uint32_t addr) {
    asm volatile("ldmatrix.sync.aligned.m8n8.x4.shared.b16 {%0,%1,%2,%3},[%4];"
                 : "=r"(r0), "=r"(r1), "=r"(r2), "=r"(r3) : "r"(addr));
}
__device__ __forceinline__ void mma16816(float* d, const uint32_t* a, const uint32_t* b) {
    asm volatile("mma.sync.aligned.m16n8k16.row.col.f32.bf16.bf16.f32 "
                 "{%0,%1,%2,%3},{%4,%5,%6,%7},{%8,%9},{%0,%1,%2,%3};"
                 : "+f"(d[0]), "+f"(d[1]), "+f"(d[2]), "+f"(d[3])
                 : "r"(a[0]), "r"(a[1]), "r"(a[2]), "r"(a[3]), "r"(b[0]), "r"(b[1]));
}
__device__ __forceinline__ uint32_t pack_bf2(__nv_bfloat16 a, __nv_bfloat16 b) {
    return (uint32_t)__bfloat16_as_ushort(a) | ((uint32_t)__bfloat16_as_ushort(b) << 16);
}

// ---------------------------------------------------------------------------
// Plane transpose: (3*128, 64, 64) -> (3, 4096, 128) channel-last
// ---------------------------------------------------------------------------
__global__ void tplanes_kernel(const float* __restrict__ P, float* __restrict__ out) {
    __shared__ float t[32][33];
    int b = blockIdx.x;
    int ct = b & 3;
    int yt = (b >> 2) & 127;
    int p  = b >> 9;
    int x  = threadIdx.x & 31;
    int r0 = threadIdx.x >> 5;
    int c0 = ct * 32, yx0 = yt * 32;
    #pragma unroll
    for (int cy = r0; cy < 32; cy += 8)
        t[cy][x] = P[((size_t)(p * 128 + c0 + cy)) * 4096 + yx0 + x];
    __syncthreads();
    #pragma unroll
    for (int yy = r0; yy < 32; yy += 8)
        out[((size_t)(p * 4096 + yx0 + yy)) * 128 + c0 + x] = t[x][yy];
}

// ---------------------------------------------------------------------------
// Weight prep: W [Kin x 512] fp32 -> WT [512 x Kpad] bf16 hi/lo (zero-padded)
// ---------------------------------------------------------------------------
__global__ void prep_w_kernel(const float* __restrict__ W, int Kin, int Kpad,
                              __nv_bfloat16* __restrict__ oh, __nv_bfloat16* __restrict__ ol) {
    int i = blockIdx.x * blockDim.x + threadIdx.x;
    if (i >= 512 * Kpad) return;
    int n = i / Kpad, k = i % Kpad;
    float x = (k < Kin) ? W[(size_t)k * 512 + n] : 0.0f;
    __nv_bfloat16 h, l;
    split_bf16(x, h, l);
    oh[i] = h; ol[i] = l;
}

// ---------------------------------------------------------------------------
// Sampler: warp per query; channel-last planes -> coalesced float4 corner loads.
// ---------------------------------------------------------------------------
__global__ __launch_bounds__(256)
void sampler_kernel(const float* __restrict__ PT, const float* __restrict__ query,
                    __nv_bfloat16* __restrict__ h0h, __nv_bfloat16* __restrict__ h0l) {
    int n = blockIdx.x * 8 + (threadIdx.x >> 5);
    int lane = threadIdx.x & 31;

    float q0 = __ldg(query + 3 * n + 0);
    float q1 = __ldg(query + 3 * n + 1);
    float q2 = __ldg(query + 3 * n + 2);

    float u[3] = { q0 / 1.1f, q1 / 1.1f, q0 / 1.1f };
    float v[3] = { q2 / 1.1f, q2 / 1.1f, q1 / 1.1f };

    float4 acc = make_float4(0.f, 0.f, 0.f, 0.f);

    #pragma unroll
    for (int p = 0; p < 3; ++p) {
        float x = (u[p] + 1.0f) * 0.5f * 63.0f;
        float y = (v[p] + 1.0f) * 0.5f * 63.0f;
        float x0f = floorf(x), y0f = floorf(y);
        float wx = x - x0f, wy = y - y0f;
        int x0 = min(max((int)x0f, 0), 63);
        int y0 = min(max((int)y0f, 0), 63);
        int x1 = min(x0 + 1, 63);
        int y1 = min(y0 + 1, 63);
        float w00 = (1.f - wx) * (1.f - wy);
        float w01 = wx * (1.f - wy);
        float w10 = (1.f - wx) * wy;
        float w11 = wx * wy;
        const float* base = PT + (size_t)p * 4096 * 128 + lane * 4;
        float4 v00 = *(const float4*)(base + (size_t)(y0 * 64 + x0) * 128);
        float4 v01 = *(const float4*)(base + (size_t)(y0 * 64 + x1) * 128);
        float4 v10 = *(const float4*)(base + (size_t)(y1 * 64 + x0) * 128);
        float4 v11 = *(const float4*)(base + (size_t)(y1 * 64 + x1) * 128);
        acc.x += w00 * v00.x + w01 * v01.x + w10 * v10.x + w11 * v11.x;
        acc.y += w00 * v00.y + w01 * v01.y + w10 * v10.y + w11 * v11.y;
        acc.z += w00 * v00.z + w01 * v01.z + w10 * v10.z + w11 * v11.z;
        acc.w += w00 * v00.w + w01 * v01.w + w10 * v10.w + w11 * v11.w;
    }

    __nv_bfloat16 hv[4], lv[4];
    split_bf16(acc.x, hv[0], lv[0]);
    split_bf16(acc.y, hv[1], lv[1]);
    split_bf16(acc.z, hv[2], lv[2]);
    split_bf16(acc.w, hv[3], lv[3]);
    size_t rb = (size_t)n * K1P;
    *(uint2*)(h0h + rb + lane * 4) = *(uint2*)hv;
    *(uint2*)(h0l + rb + lane * 4) = *(uint2*)lv;

    #pragma unroll
    for (int j = 0; j < 2; ++j) {
        int col = 128 + lane * 2 + j;
        float val = (col == 128) ? q0 : (col == 129) ? q1 : (col == 130) ? q2 : 0.0f;
        __nv_bfloat16 h, l;
        split_bf16(val, h, l);
        h0h[rb + col] = h;
        h0l[rb + col] = l;
    }
}

// ---------------------------------------------------------------------------
// bf16 HMMA GEMM: C[M x 512] = relu(A[M x K] @ B^T + bias)
//   A: [M,K] bf16 hi/lo row-major; B: [512,K] bf16 hi/lo row-major.
//   3-term compensated: AhBh + AhBl + AlBh, fp32 accum.
//   CTA 128x128, BK=32, 8 warps (32x64 warp tile), double-buffered cp.async.
//   FINAL: partial head dot (relu * Wo) atomically added into out.
// ---------------------------------------------------------------------------
#define RS          80                  // smem row stride (bytes): 64B data + 16B pad
#define MAT_BYTES   (128 * RS)          // 10240
#define STAGE_BYTES (4 * MAT_BYTES)     // 40960
#define GSMEM       (2 * STAGE_BYTES)   // 81920

template<int K, bool FINAL>
__global__ __launch_bounds__(256, 1)
void gemm_kernel(const __nv_bfloat16* __restrict__ Ah, const __nv_bfloat16* __restrict__ Al,
                 const __nv_bfloat16* __restrict__ Bh, const __nv_bfloat16* __restrict__ Bl,
                 const float* __restrict__ bias,
                 __nv_bfloat16* __restrict__ Ch, __nv_bfloat16* __restrict__ Cl,
                 const float* __restrict__ Wo, float* __restrict__ out) {
    extern __shared__ char smem[];
    const int tid  = threadIdx.x;
    const int lane = tid & 31, wid = tid >> 5;
    const int m0 = blockIdx.y * 128;
    const int n0 = blockIdx.x * 128;
    const uint32_t sb = smem_u32(smem);

    const int lr0 = tid >> 2;       // load row 0..63
    const int lc0 = tid & 3;        // 16B chunk 0..3

    float acc[2][8][4];
    #pragma unroll
    for (int a = 0; a < 2; ++a)
        #pragma unroll
        for (int b = 0; b < 8; ++b)
            #pragma unroll
            for (int c = 0; c < 4; ++c) acc[a][b][c] = 0.0f;

    auto load_stage = [&](int buf, int kt) {
        uint32_t s = sb + buf * STAGE_BYTES;
        #pragma unroll
        for (int rep = 0; rep < 2; ++rep) {
            int r = lr0 + rep * 64;
            uint32_t so = (uint32_t)(r * RS + lc0 * 16);
            size_t ga = (size_t)(m0 + r) * K + kt + lc0 * 8;
            size_t gb = (size_t)(n0 + r) * K + kt + lc0 * 8;
            cp16(s + so,                 Ah + ga);
            cp16(s + MAT_BYTES + so,     Al + ga);
            cp16(s + 2 * MAT_BYTES + so, Bh + gb);
            cp16(s + 3 * MAT_BYTES + so, Bl + gb);
        }
        asm volatile("cp.async.commit_group;" ::: "memory");
    };

    constexpr int NS = K / 32;
    load_stage(0, 0);

    const int g = lane >> 3, t = lane & 7;
    const int warp_m = wid & 3, warp_n = wid >> 2;
    const uint32_t a_row  = warp_m * 32 + ((g & 1) << 3) + t;
    const uint32_t a_coff = (uint32_t)(g >> 1);
    const uint32_t b_row  = warp_n * 64 + ((g >> 1) << 3) + t;
    const uint32_t b_coff = (uint32_t)(g & 1);

    for (int st = 0; st < NS; ++st) {
        if (st + 1 < NS) {
            load_stage((st + 1) & 1, (st + 1) * 32);
            asm volatile("cp.async.wait_group 1;" ::: "memory");
        } else {
            asm volatile("cp.async.wait_group 0;" ::: "memory");
        }
        __syncthreads();

        uint32_t s = sb + (st & 1) * STAGE_BYTES;
        #pragma unroll
        for (int ks = 0; ks < 2; ++ks) {
            uint32_t aH[2][4], aL[2][4], bH[8][2], bL[8][2];
            #pragma unroll
            for (int mt = 0; mt < 2; ++mt) {
                uint32_t ad = s + (a_row + mt * 16) * RS + (ks * 2 + a_coff) * 16;
                ldsm4(aH[mt][0], aH[mt][1], aH[mt][2], aH[mt][3], ad);
                ldsm4(aL[mt][0], aL[mt][1], aL[mt][2], aL[mt][3], ad + MAT_BYTES);
            }
            #pragma unroll
            for (int nb = 0; nb < 4; ++nb) {
                uint32_t bd = s + 2 * MAT_BYTES + (b_row + nb * 16) * RS + (ks * 2 + b_coff) * 16;
                ldsm4(bH[2*nb][0], bH[2*nb][1], bH[2*nb+1][0], bH[2*nb+1][1], bd);
                ldsm4(bL[2*nb][0], bL[2*nb][1], bL[2*nb+1][0], bL[2*nb+1][1], bd + MAT_BYTES);
            }
            #pragma unroll
            for (int mt = 0; mt < 2; ++mt)
                #pragma unroll
                for (int nb = 0; nb < 8; ++nb) {
                    mma16816(acc[mt][nb], aH[mt], bH[nb]);
                    mma16816(acc[mt][nb], aH[mt], bL[nb]);
                    mma16816(acc[mt][nb], aL[mt], bH[nb]);
                }
        }
        __syncthreads();
    }

    // ---------------- epilogue ----------------
    const int row_l = lane >> 2;
    const int colq  = (lane & 3) * 2;

    #pragma unroll
    for (int mt = 0; mt < 2; ++mt) {
        int r0g = m0 + warp_m * 32 + mt * 16 + row_l;
        if (!FINAL) {
            #pragma unroll
            for (int nb = 0; nb < 8; ++nb) {
                int c0 = n0 + warp_n * 64 + nb * 8 + colq;
                float b0 = __ldg(bias + c0), b1 = __ldg(bias + c0 + 1);
                float v0 = fmaxf(acc[mt][nb][0] + b0, 0.f);
                float v1 = fmaxf(acc[mt][nb][1] + b1, 0.f);
                float v2 = fmaxf(acc[mt][nb][2] + b0, 0.f);
                float v3 = fmaxf(acc[mt][nb][3] + b1, 0.f);
                __nv_bfloat16 h0v, l0v, h1v, l1v;
                split_bf16(v0, h0v, l0v); split_bf16(v1, h1v, l1v);
                *(uint32_t*)(Ch + (size_t)r0g * HID + c0) = pack_bf2(h0v, h1v);
                *(uint32_t*)(Cl + (size_t)r0g * HID + c0) = pack_bf2(l0v, l1v);
                split_bf16(v2, h0v, l0v); split_bf16(v3, h1v, l1v);
                *(uint32_t*)(Ch + (size_t)(r0g + 8) * HID + c0) = pack_bf2(h0v, h1v);
                *(uint32_t*)(Cl + (size_t)(r0g + 8) * HID + c0) = pack_bf2(l0v, l1v);
            }
        } else {
            float p0 = 0.f, p1 = 0.f;
            #pragma unroll
            for (int nb = 0; nb < 8; ++nb) {
                int c0 = n0 + warp_n * 64 + nb * 8 + colq;
                float b0 = __ldg(bias + c0), b1 = __ldg(bias + c0 + 1);
                float w0 = __ldg(Wo + c0),   w1 = __ldg(Wo + c0 + 1);
                p0 += fmaxf(acc[mt][nb][0] + b0, 0.f) * w0
                    + fmaxf(acc[mt][nb][1] + b1, 0.f) * w1;
                p1 += fmaxf(acc[mt][nb][2] + b0, 0.f) * w0
                    + fmaxf(acc[mt][nb][3] + b1, 0.f) * w1;
            }
            p0 += __shfl_xor_sync(0xFFFFFFFFu, p0, 1);
            p0 += __shfl_xor_sync(0xFFFFFFFFu, p0, 2);
            p1 += __shfl_xor_sync(0xFFFFFFFFu, p1, 1);
            p1 += __shfl_xor_sync(0xFFFFFFFFu, p1, 2);
            if ((lane & 3) == 0) {
                atomicAdd(out + r0g, p0);
                atomicAdd(out + r0g + 8, p1);
            }
        }
    }
}

// ---------------------------------------------------------------------------
// out init / final tanh
// ---------------------------------------------------------------------------
__global__ void zero_out_kernel(float* __restrict__ out) {
    int i = blockIdx.x * blockDim.x + threadIdx.x;
    if (i < NQ) out[i] = 0.0f;
}
__global__ void tanh_kernel(float* __restrict__ out, const float* __restrict__ bo) {
    int i = blockIdx.x * blockDim.x + threadIdx.x;
    if (i < NQ) out[i] = tanhf(out[i] + __ldg(bo));
}

// ---------------------------------------------------------------------------
// Launcher
// ---------------------------------------------------------------------------
extern "C" void kernel_launch(void* const* d_in, const int* in_sizes, int n_in,
                              void* d_out, int out_size) {
    const float* planes = (const float*)d_in[0];
    const float* query  = (const float*)d_in[1];
    const float* W1     = (const float*)d_in[2];
    const float* b1     = (const float*)d_in[3];
    const float* W2     = (const float*)d_in[4];
    const float* b2     = (const float*)d_in[5];
    const float* W3     = (const float*)d_in[6];
    const float* b3     = (const float*)d_in[7];
    const float* Wo     = (const float*)d_in[8];
    const float* bo     = (const float*)d_in[9];
    float* out = (float*)d_out;

    float *planesT;
    __nv_bfloat16 *h0h, *h0l, *w1h, *w1l, *w2h, *w2l, *w3h, *w3l, *ah, *al, *bh, *bl;
    cudaGetSymbolAddress((void**)&planesT, g_planesT);
    cudaGetSymbolAddress((void**)&h0h, g_h0h);
    cudaGetSymbolAddress((void**)&h0l, g_h0l);
    cudaGetSymbolAddress((void**)&w1h, g_w1h);
    cudaGetSymbolAddress((void**)&w1l, g_w1l);
    cudaGetSymbolAddress((void**)&w2h, g_w2h);
    cudaGetSymbolAddress((void**)&w2l, g_w2l);
    cudaGetSymbolAddress((void**)&w3h, g_w3h);
    cudaGetSymbolAddress((void**)&w3l, g_w3l);
    cudaGetSymbolAddress((void**)&ah, g_ah);
    cudaGetSymbolAddress((void**)&al, g_al);
    cudaGetSymbolAddress((void**)&bh, g_bh);
    cudaGetSymbolAddress((void**)&bl, g_bl);

    cudaFuncSetAttribute(gemm_kernel<K1P, false>,
                         cudaFuncAttributeMaxDynamicSharedMemorySize, GSMEM);
    cudaFuncSetAttribute(gemm_kernel<HID, false>,
                         cudaFuncAttributeMaxDynamicSharedMemorySize, GSMEM);
    cudaFuncSetAttribute(gemm_kernel<HID, true>,
                         cudaFuncAttributeMaxDynamicSharedMemorySize, GSMEM);

    zero_out_kernel<<<NQ / 256, 256>>>(out);

    tplanes_kernel<<<3 * 128 * 4, 256>>>(planes, planesT);

    prep_w_kernel<<<(512 * K1P + 255) / 256, 256>>>(W1, 131, K1P, w1h, w1l);
    prep_w_kernel<<<(512 * HID + 255) / 256, 256>>>(W2, 512, HID, w2h, w2l);
    prep_w_kernel<<<(512 * HID + 255) / 256, 256>>>(W3, 512, HID, w3h, w3l);

    sampler_kernel<<<NQ / 8, 256>>>(planesT, query, h0h, h0l);

    dim3 grid(4, NQ / 128);
    gemm_kernel<K1P, false><<<grid, 256, GSMEM>>>(
        h0h, h0l, w1h, w1l, b1, ah, al, nullptr, nullptr);
    gemm_kernel<HID, false><<<grid, 256, GSMEM>>>(
        ah, al, w2h, w2l, b2, bh, bl, nullptr, nullptr);
    gemm_kernel<HID, true><<<grid, 256, GSMEM>>>(
        bh, bl, w3h, w3l, b3, nullptr, nullptr, Wo, out);

    tanh_kernel<<<NQ / 256, 256>>>(out, bo);
}

// round 4
// speedup vs baseline: 2.4759x; 1.0651x over previous
#include <cuda_runtime.h>
#include <cuda_bf16.h>
#include <math.h>
#include <cstdint>

// ---------------------------------------------------------------------------
// Problem constants
// ---------------------------------------------------------------------------
#define NQ     131072
#define K1P    160        // 128 feats + 3 query + pad (mult of 32)
#define HID    512

// ---------------------------------------------------------------------------
// Scratch (device globals; no cudaMalloc allowed)
// ---------------------------------------------------------------------------
__device__ float         g_planesT[3u * 64 * 64 * 128];
__device__ __nv_bfloat16 g_h0h[(size_t)NQ * K1P];
__device__ __nv_bfloat16 g_h0l[(size_t)NQ * K1P];
__device__ __nv_bfloat16 g_w1h[(size_t)HID * K1P], g_w1l[(size_t)HID * K1P];
__device__ __nv_bfloat16 g_w2h[(size_t)HID * HID], g_w2l[(size_t)HID * HID];
__device__ __nv_bfloat16 g_w3h[(size_t)HID * HID], g_w3l[(size_t)HID * HID];
__device__ __nv_bfloat16 g_ah[(size_t)NQ * HID], g_al[(size_t)NQ * HID];
__device__ __nv_bfloat16 g_bh[(size_t)NQ * HID], g_bl[(size_t)NQ * HID];
__device__ float         g_part[4][(size_t)NQ];

__device__ __forceinline__ void split_bf16(float x, __nv_bfloat16& h, __nv_bfloat16& l) {
    h = __float2bfloat16(x);
    l = __float2bfloat16(x - __bfloat162float(h));
}

__device__ __forceinline__ uint32_t smem_u32(const void* p) {
    uint32_t a;
    asm("{ .reg .u64 t; cvta.to.shared.u64 t, %1; cvt.u32.u64 %0, t; }" : "=r"(a) : "l"(p));
    return a;
}
__device__ __forceinline__ void cp16(uint32_t saddr, const void* g) {
    asm volatile("cp.async.cg.shared.global [%0], [%1], 16;" :: "r"(saddr), "l"(g));
}
__device__ __forceinline__ void cp_commit() {
    asm volatile("cp.async.commit_group;" ::: "memory");
}
template<int N>
__device__ __forceinline__ void cp_wait() {
    asm volatile("cp.async.wait_group %0;" :: "n"(N) : "memory");
}
__device__ __forceinline__ void ldsm4(uint32_t& r0, uint32_t& r1, uint32_t& r2, uint32_t& r3,
                                      uint32_t addr) {
    asm volatile("ldmatrix.sync.aligned.m8n8.x4.shared.b16 {%0,%1,%2,%3},[%4];"
                 : "=r"(r0), "=r"(r1), "=r"(r2), "=r"(r3) : "r"(addr));
}
__device__ __forceinline__ void mma16816(float* d, const uint32_t* a, const uint32_t* b) {
    asm volatile("mma.sync.aligned.m16n8k16.row.col.f32.bf16.bf16.f32 "
                 "{%0,%1,%2,%3},{%4,%5,%6,%7},{%8,%9},{%0,%1,%2,%3};"
                 : "+f"(d[0]), "+f"(d[1]), "+f"(d[2]), "+f"(d[3])
                 : "r"(a[0]), "r"(a[1]), "r"(a[2]), "r"(a[3]), "r"(b[0]), "r"(b[1]));
}
__device__ __forceinline__ uint32_t pack_bf2(__nv_bfloat16 a, __nv_bfloat16 b) {
    return (uint32_t)__bfloat16_as_ushort(a) | ((uint32_t)__bfloat16_as_ushort(b) << 16);
}

// ---------------------------------------------------------------------------
// Plane transpose: (3*128, 64, 64) -> (3, 4096, 128) channel-last
// ---------------------------------------------------------------------------
__global__ void tplanes_kernel(const float* __restrict__ P, float* __restrict__ out) {
    __shared__ float t[32][33];
    int b = blockIdx.x;
    int ct = b & 3;
    int yt = (b >> 2) & 127;
    int p  = b >> 9;
    int x  = threadIdx.x & 31;
    int r0 = threadIdx.x >> 5;
    int c0 = ct * 32, yx0 = yt * 32;
    #pragma unroll
    for (int cy = r0; cy < 32; cy += 8)
        t[cy][x] = P[((size_t)(p * 128 + c0 + cy)) * 4096 + yx0 + x];
    __syncthreads();
    #pragma unroll
    for (int yy = r0; yy < 32; yy += 8)
        out[((size_t)(p * 4096 + yx0 + yy)) * 128 + c0 + x] = t[x][yy];
}

// ---------------------------------------------------------------------------
// Combined weight prep (single launch): W1 -> [512,160], W2/W3 -> [512,512]
// ---------------------------------------------------------------------------
#define PREP_N1 (512 * K1P)
#define PREP_N2 (512 * HID)
__global__ void prep_all_kernel(const float* __restrict__ W1, const float* __restrict__ W2,
                                const float* __restrict__ W3,
                                __nv_bfloat16* __restrict__ w1h, __nv_bfloat16* __restrict__ w1l,
                                __nv_bfloat16* __restrict__ w2h, __nv_bfloat16* __restrict__ w2l,
                                __nv_bfloat16* __restrict__ w3h, __nv_bfloat16* __restrict__ w3l) {
    int i = blockIdx.x * blockDim.x + threadIdx.x;
    const float* W; __nv_bfloat16 *oh, *ol; int Kin, Kpad, j;
    if (i < PREP_N1) {
        W = W1; oh = w1h; ol = w1l; Kin = 131; Kpad = K1P; j = i;
    } else if (i < PREP_N1 + PREP_N2) {
        W = W2; oh = w2h; ol = w2l; Kin = 512; Kpad = HID; j = i - PREP_N1;
    } else if (i < PREP_N1 + 2 * PREP_N2) {
        W = W3; oh = w3h; ol = w3l; Kin = 512; Kpad = HID; j = i - PREP_N1 - PREP_N2;
    } else return;
    int n = j / Kpad, k = j % Kpad;
    float x = (k < Kin) ? W[(size_t)k * 512 + n] : 0.0f;
    __nv_bfloat16 h, l;
    split_bf16(x, h, l);
    oh[j] = h; ol[j] = l;
}

// ---------------------------------------------------------------------------
// Sampler: warp per query; channel-last planes -> coalesced float4 corner loads.
// ---------------------------------------------------------------------------
__global__ __launch_bounds__(256)
void sampler_kernel(const float* __restrict__ PT, const float* __restrict__ query,
                    __nv_bfloat16* __restrict__ h0h, __nv_bfloat16* __restrict__ h0l) {
    int n = blockIdx.x * 8 + (threadIdx.x >> 5);
    int lane = threadIdx.x & 31;

    float q0 = __ldg(query + 3 * n + 0);
    float q1 = __ldg(query + 3 * n + 1);
    float q2 = __ldg(query + 3 * n + 2);

    float u[3] = { q0 / 1.1f, q1 / 1.1f, q0 / 1.1f };
    float v[3] = { q2 / 1.1f, q2 / 1.1f, q1 / 1.1f };

    float4 acc = make_float4(0.f, 0.f, 0.f, 0.f);

    #pragma unroll
    for (int p = 0; p < 3; ++p) {
        float x = (u[p] + 1.0f) * 0.5f * 63.0f;
        float y = (v[p] + 1.0f) * 0.5f * 63.0f;
        float x0f = floorf(x), y0f = floorf(y);
        float wx = x - x0f, wy = y - y0f;
        int x0 = min(max((int)x0f, 0), 63);
        int y0 = min(max((int)y0f, 0), 63);
        int x1 = min(x0 + 1, 63);
        int y1 = min(y0 + 1, 63);
        float w00 = (1.f - wx) * (1.f - wy);
        float w01 = wx * (1.f - wy);
        float w10 = (1.f - wx) * wy;
        float w11 = wx * wy;
        const float* base = PT + (size_t)p * 4096 * 128 + lane * 4;
        float4 v00 = *(const float4*)(base + (size_t)(y0 * 64 + x0) * 128);
        float4 v01 = *(const float4*)(base + (size_t)(y0 * 64 + x1) * 128);
        float4 v10 = *(const float4*)(base + (size_t)(y1 * 64 + x0) * 128);
        float4 v11 = *(const float4*)(base + (size_t)(y1 * 64 + x1) * 128);
        acc.x += w00 * v00.x + w01 * v01.x + w10 * v10.x + w11 * v11.x;
        acc.y += w00 * v00.y + w01 * v01.y + w10 * v10.y + w11 * v11.y;
        acc.z += w00 * v00.z + w01 * v01.z + w10 * v10.z + w11 * v11.z;
        acc.w += w00 * v00.w + w01 * v01.w + w10 * v10.w + w11 * v11.w;
    }

    __nv_bfloat16 hv[4], lv[4];
    split_bf16(acc.x, hv[0], lv[0]);
    split_bf16(acc.y, hv[1], lv[1]);
    split_bf16(acc.z, hv[2], lv[2]);
    split_bf16(acc.w, hv[3], lv[3]);
    size_t rb = (size_t)n * K1P;
    *(uint2*)(h0h + rb + lane * 4) = *(uint2*)hv;
    *(uint2*)(h0l + rb + lane * 4) = *(uint2*)lv;

    // cols 128..159: query at 128..130, zeros elsewhere (1 per lane)
    {
        int col = 128 + lane;
        float val = (lane == 0) ? q0 : (lane == 1) ? q1 : (lane == 2) ? q2 : 0.0f;
        __nv_bfloat16 h, l;
        split_bf16(val, h, l);
        h0h[rb + col] = h;
        h0l[rb + col] = l;
    }
}

// ---------------------------------------------------------------------------
// bf16 HMMA GEMM: C[M x 512] = relu(A[M x K] @ B^T + bias)
//   3-term compensated: AhBh + AhBl + AlBh, fp32 accum.
//   CTA 128x128, BK=32, 8 warps, 3-stage cp.async pipeline.
//   FINAL: per-slab head partials (relu * Wo) -> part[slab][m].
// ---------------------------------------------------------------------------
#define RS          80
#define MAT_BYTES   (128 * RS)          // 10240
#define STAGE_BYTES (4 * MAT_BYTES)     // 40960
#define GSMEM       (3 * STAGE_BYTES)   // 122880

template<int K, bool FINAL>
__global__ __launch_bounds__(256, 1)
void gemm_kernel(const __nv_bfloat16* __restrict__ Ah, const __nv_bfloat16* __restrict__ Al,
                 const __nv_bfloat16* __restrict__ Bh, const __nv_bfloat16* __restrict__ Bl,
                 const float* __restrict__ bias,
                 __nv_bfloat16* __restrict__ Ch, __nv_bfloat16* __restrict__ Cl,
                 const float* __restrict__ Wo, float* __restrict__ part) {
    extern __shared__ char smem[];
    const int tid  = threadIdx.x;
    const int lane = tid & 31, wid = tid >> 5;
    const int m0 = blockIdx.y * 128;
    const int n0 = blockIdx.x * 128;
    const uint32_t sb = smem_u32(smem);

    const int lr0 = tid >> 2;
    const int lc0 = tid & 3;

    float acc[2][8][4];
    #pragma unroll
    for (int a = 0; a < 2; ++a)
        #pragma unroll
        for (int b = 0; b < 8; ++b)
            #pragma unroll
            for (int c = 0; c < 4; ++c) acc[a][b][c] = 0.0f;

    auto load_stage = [&](int buf, int kt) {
        uint32_t s = sb + buf * STAGE_BYTES;
        #pragma unroll
        for (int rep = 0; rep < 2; ++rep) {
            int r = lr0 + rep * 64;
            uint32_t so = (uint32_t)(r * RS + lc0 * 16);
            size_t ga = (size_t)(m0 + r) * K + kt + lc0 * 8;
            size_t gb = (size_t)(n0 + r) * K + kt + lc0 * 8;
            cp16(s + so,                 Ah + ga);
            cp16(s + MAT_BYTES + so,     Al + ga);
            cp16(s + 2 * MAT_BYTES + so, Bh + gb);
            cp16(s + 3 * MAT_BYTES + so, Bl + gb);
        }
        cp_commit();
    };

    constexpr int NS = K / 32;
    load_stage(0, 0);
    load_stage(1, 32);

    const int g = lane >> 3, t = lane & 7;
    const int warp_m = wid & 3, warp_n = wid >> 2;
    const uint32_t a_row  = warp_m * 32 + ((g & 1) << 3) + t;
    const uint32_t a_coff = (uint32_t)(g >> 1);
    const uint32_t b_row  = warp_n * 64 + ((g >> 1) << 3) + t;
    const uint32_t b_coff = (uint32_t)(g & 1);

    int buf = 0;
    for (int st = 0; st < NS; ++st) {
        if (st + 1 < NS) cp_wait<1>(); else cp_wait<0>();
        __syncthreads();

        if (st + 2 < NS) {
            int nb3 = buf + 2; if (nb3 >= 3) nb3 -= 3;
            load_stage(nb3, (st + 2) * 32);
        }

        uint32_t s = sb + buf * STAGE_BYTES;
        #pragma unroll
        for (int ks = 0; ks < 2; ++ks) {
            uint32_t aH[2][4], aL[2][4], bH[8][2], bL[8][2];
            #pragma unroll
            for (int mt = 0; mt < 2; ++mt) {
                uint32_t ad = s + (a_row + mt * 16) * RS + (ks * 2 + a_coff) * 16;
                ldsm4(aH[mt][0], aH[mt][1], aH[mt][2], aH[mt][3], ad);
                ldsm4(aL[mt][0], aL[mt][1], aL[mt][2], aL[mt][3], ad + MAT_BYTES);
            }
            #pragma unroll
            for (int nb = 0; nb < 4; ++nb) {
                uint32_t bd = s + 2 * MAT_BYTES + (b_row + nb * 16) * RS + (ks * 2 + b_coff) * 16;
                ldsm4(bH[2*nb][0], bH[2*nb][1], bH[2*nb+1][0], bH[2*nb+1][1], bd);
                ldsm4(bL[2*nb][0], bL[2*nb][1], bL[2*nb+1][0], bL[2*nb+1][1], bd + MAT_BYTES);
            }
            #pragma unroll
            for (int mt = 0; mt < 2; ++mt)
                #pragma unroll
                for (int nb = 0; nb < 8; ++nb) {
                    mma16816(acc[mt][nb], aH[mt], bH[nb]);
                    mma16816(acc[mt][nb], aH[mt], bL[nb]);
                    mma16816(acc[mt][nb], aL[mt], bH[nb]);
                }
        }
        if (++buf == 3) buf = 0;
    }

    // ---------------- epilogue ----------------
    const int row_l = lane >> 2;
    const int colq  = (lane & 3) * 2;

    #pragma unroll
    for (int mt = 0; mt < 2; ++mt) {
        int r0g = m0 + warp_m * 32 + mt * 16 + row_l;
        if (!FINAL) {
            #pragma unroll
            for (int nb = 0; nb < 8; ++nb) {
                int c0 = n0 + warp_n * 64 + nb * 8 + colq;
                float b0 = __ldg(bias + c0), b1 = __ldg(bias + c0 + 1);
                float v0 = fmaxf(acc[mt][nb][0] + b0, 0.f);
                float v1 = fmaxf(acc[mt][nb][1] + b1, 0.f);
                float v2 = fmaxf(acc[mt][nb][2] + b0, 0.f);
                float v3 = fmaxf(acc[mt][nb][3] + b1, 0.f);
                __nv_bfloat16 h0v, l0v, h1v, l1v;
                split_bf16(v0, h0v, l0v); split_bf16(v1, h1v, l1v);
                *(uint32_t*)(Ch + (size_t)r0g * HID + c0) = pack_bf2(h0v, h1v);
                *(uint32_t*)(Cl + (size_t)r0g * HID + c0) = pack_bf2(l0v, l1v);
                split_bf16(v2, h0v, l0v); split_bf16(v3, h1v, l1v);
                *(uint32_t*)(Ch + (size_t)(r0g + 8) * HID + c0) = pack_bf2(h0v, h1v);
                *(uint32_t*)(Cl + (size_t)(r0g + 8) * HID + c0) = pack_bf2(l0v, l1v);
            }
        } else {
            float p0 = 0.f, p1 = 0.f;
            #pragma unroll
            for (int nb = 0; nb < 8; ++nb) {
                int c0 = n0 + warp_n * 64 + nb * 8 + colq;
                float b0 = __ldg(bias + c0), b1 = __ldg(bias + c0 + 1);
                float w0 = __ldg(Wo + c0),   w1 = __ldg(Wo + c0 + 1);
                p0 += fmaxf(acc[mt][nb][0] + b0, 0.f) * w0
                    + fmaxf(acc[mt][nb][1] + b1, 0.f) * w1;
                p1 += fmaxf(acc[mt][nb][2] + b0, 0.f) * w0
                    + fmaxf(acc[mt][nb][3] + b1, 0.f) * w1;
            }
            p0 += __shfl_xor_sync(0xFFFFFFFFu, p0, 1);
            p0 += __shfl_xor_sync(0xFFFFFFFFu, p0, 2);
            p1 += __shfl_xor_sync(0xFFFFFFFFu, p1, 1);
            p1 += __shfl_xor_sync(0xFFFFFFFFu, p1, 2);
            // two warp_n halves write the same slab column set? no: slab per blockIdx.x,
            // within block two warp_n values cover different n-ranges -> need block reduce.
            __shared__ float red[2][128];  // [warp_n][m-row within tile]
            if ((lane & 3) == 0) {
                int mi = warp_m * 32 + mt * 16 + row_l;
                if (warp_n == 0) { red[0][mi] = p0; red[0][mi + 8] = p1; }
            }
            __syncthreads();
            if ((lane & 3) == 0 && warp_n == 1) {
                int mi = warp_m * 32 + mt * 16 + row_l;
                part[(size_t)blockIdx.x * NQ + m0 + mi]     = red[0][mi] + p0;
                part[(size_t)blockIdx.x * NQ + m0 + mi + 8] = red[0][mi + 8] + p1;
            }
            __syncthreads();
        }
    }
}

// ---------------------------------------------------------------------------
// final: out = tanh(sum of 4 slabs + bo)
// ---------------------------------------------------------------------------
__global__ void tanh_kernel(const float* __restrict__ part, const float* __restrict__ bo,
                            float* __restrict__ out) {
    int i = blockIdx.x * blockDim.x + threadIdx.x;
    if (i < NQ) {
        float s = part[i] + part[NQ + (size_t)i] + part[2 * (size_t)NQ + i] + part[3 * (size_t)NQ + i];
        out[i] = tanhf(s + __ldg(bo));
    }
}

// ---------------------------------------------------------------------------
// Launcher
// ---------------------------------------------------------------------------
extern "C" void kernel_launch(void* const* d_in, const int* in_sizes, int n_in,
                              void* d_out, int out_size) {
    const float* planes = (const float*)d_in[0];
    const float* query  = (const float*)d_in[1];
    const float* W1     = (const float*)d_in[2];
    const float* b1     = (const float*)d_in[3];
    const float* W2     = (const float*)d_in[4];
    const float* b2     = (const float*)d_in[5];
    const float* W3     = (const float*)d_in[6];
    const float* b3     = (const float*)d_in[7];
    const float* Wo     = (const float*)d_in[8];
    const float* bo     = (const float*)d_in[9];
    float* out = (float*)d_out;

    float *planesT, *part;
    __nv_bfloat16 *h0h, *h0l, *w1h, *w1l, *w2h, *w2l, *w3h, *w3l, *ah, *al, *bh, *bl;
    cudaGetSymbolAddress((void**)&planesT, g_planesT);
    cudaGetSymbolAddress((void**)&part, g_part);
    cudaGetSymbolAddress((void**)&h0h, g_h0h);
    cudaGetSymbolAddress((void**)&h0l, g_h0l);
    cudaGetSymbolAddress((void**)&w1h, g_w1h);
    cudaGetSymbolAddress((void**)&w1l, g_w1l);
    cudaGetSymbolAddress((void**)&w2h, g_w2h);
    cudaGetSymbolAddress((void**)&w2l, g_w2l);
    cudaGetSymbolAddress((void**)&w3h, g_w3h);
    cudaGetSymbolAddress((void**)&w3l, g_w3l);
    cudaGetSymbolAddress((void**)&ah, g_ah);
    cudaGetSymbolAddress((void**)&al, g_al);
    cudaGetSymbolAddress((void**)&bh, g_bh);
    cudaGetSymbolAddress((void**)&bl, g_bl);

    cudaFuncSetAttribute(gemm_kernel<K1P, false>,
                         cudaFuncAttributeMaxDynamicSharedMemorySize, GSMEM);
    cudaFuncSetAttribute(gemm_kernel<HID, false>,
                         cudaFuncAttributeMaxDynamicSharedMemorySize, GSMEM);
    cudaFuncSetAttribute(gemm_kernel<HID, true>,
                         cudaFuncAttributeMaxDynamicSharedMemorySize, GSMEM);

    // launch order chosen so launch #5 (1-indexed) = layer-2 GEMM for ncu -s 5
    tplanes_kernel<<<3 * 128 * 4, 256>>>(planes, planesT);                       // 1

    int prep_total = PREP_N1 + 2 * PREP_N2;
    prep_all_kernel<<<(prep_total + 255) / 256, 256>>>(W1, W2, W3,               // 2
                                                       w1h, w1l, w2h, w2l, w3h, w3l);

    sampler_kernel<<<NQ / 8, 256>>>(planesT, query, h0h, h0l);                   // 3

    dim3 grid(4, NQ / 128);
    gemm_kernel<K1P, false><<<grid, 256, GSMEM>>>(                               // 4
        h0h, h0l, w1h, w1l, b1, ah, al, nullptr, nullptr);
    gemm_kernel<HID, false><<<grid, 256, GSMEM>>>(                               // 5  <- profiled
        ah, al, w2h, w2l, b2, bh, bl, nullptr, nullptr);
    gemm_kernel<HID, true><<<grid, 256, GSMEM>>>(                                // 6
        bh, bl, w3h, w3l, b3, nullptr, nullptr, Wo, part);

    tanh_kernel<<<NQ / 256, 256>>>(part, bo, out);                               // 7
}

// round 5
// speedup vs baseline: 3.1102x; 1.2562x over previous
#include <cuda_runtime.h>
#include <cuda_bf16.h>
#include <math.h>
#include <cstdint>

// ---------------------------------------------------------------------------
// Problem constants
// ---------------------------------------------------------------------------
#define NQ     131072
#define K1P    160        // 128 feats + 3 query + pad (mult of 32)
#define HID    512

// ---------------------------------------------------------------------------
// Scratch (device globals; no cudaMalloc allowed)
// ---------------------------------------------------------------------------
__device__ float         g_planesT[3u * 64 * 64 * 128];
__device__ __nv_bfloat16 g_h0h[(size_t)NQ * K1P];
__device__ __nv_bfloat16 g_h0l[(size_t)NQ * K1P];
__device__ __nv_bfloat16 g_w1h[(size_t)HID * K1P], g_w1l[(size_t)HID * K1P];
__device__ __nv_bfloat16 g_w2h[(size_t)HID * HID], g_w2l[(size_t)HID * HID];
__device__ __nv_bfloat16 g_w3h[(size_t)HID * HID], g_w3l[(size_t)HID * HID];
__device__ __nv_bfloat16 g_ah[(size_t)NQ * HID], g_al[(size_t)NQ * HID];
__device__ __nv_bfloat16 g_bh[(size_t)NQ * HID], g_bl[(size_t)NQ * HID];
__device__ float         g_part[4][(size_t)NQ];

__device__ __forceinline__ void split_bf16(float x, __nv_bfloat16& h, __nv_bfloat16& l) {
    h = __float2bfloat16(x);
    l = __float2bfloat16(x - __bfloat162float(h));
}

__device__ __forceinline__ uint32_t smem_u32(const void* p) {
    uint32_t a;
    asm("{ .reg .u64 t; cvta.to.shared.u64 t, %1; cvt.u32.u64 %0, t; }" : "=r"(a) : "l"(p));
    return a;
}
__device__ __forceinline__ void cp16(uint32_t saddr, const void* g) {
    asm volatile("cp.async.cg.shared.global [%0], [%1], 16;" :: "r"(saddr), "l"(g));
}
__device__ __forceinline__ void cp_commit() {
    asm volatile("cp.async.commit_group;" ::: "memory");
}
template<int N>
__device__ __forceinline__ void cp_wait() {
    asm volatile("cp.async.wait_group %0;" :: "n"(N) : "memory");
}
__device__ __forceinline__ void ldsm4(uint32_t& r0, uint32_t& r1, uint32_t& r2, uint32_t& r3,
                                      uint32_t addr) {
    asm volatile("ldmatrix.sync.aligned.m8n8.x4.shared.b16 {%0,%1,%2,%3},[%4];"
                 : "=r"(r0), "=r"(r1), "=r"(r2), "=r"(r3) : "r"(addr));
}
__device__ __forceinline__ void mma16816(float* d, const uint32_t* a, const uint32_t* b) {
    asm volatile("mma.sync.aligned.m16n8k16.row.col.f32.bf16.bf16.f32 "
                 "{%0,%1,%2,%3},{%4,%5,%6,%7},{%8,%9},{%0,%1,%2,%3};"
                 : "+f"(d[0]), "+f"(d[1]), "+f"(d[2]), "+f"(d[3])
                 : "r"(a[0]), "r"(a[1]), "r"(a[2]), "r"(a[3]), "r"(b[0]), "r"(b[1]));
}
__device__ __forceinline__ uint32_t pack_bf2(__nv_bfloat16 a, __nv_bfloat16 b) {
    return (uint32_t)__bfloat16_as_ushort(a) | ((uint32_t)__bfloat16_as_ushort(b) << 16);
}
// 64B-row XOR swizzle: row r, 16B-chunk c (0..3) -> byte offset
__device__ __forceinline__ uint32_t swz(uint32_t r, uint32_t c) {
    return r * 64u + (((c + (r >> 1)) & 3u) * 16u);
}

// ---------------------------------------------------------------------------
// Plane transpose: (3*128, 64, 64) -> (3, 4096, 128) channel-last
// ---------------------------------------------------------------------------
__global__ void tplanes_kernel(const float* __restrict__ P, float* __restrict__ out) {
    __shared__ float t[32][33];
    int b = blockIdx.x;
    int ct = b & 3;
    int yt = (b >> 2) & 127;
    int p  = b >> 9;
    int x  = threadIdx.x & 31;
    int r0 = threadIdx.x >> 5;
    int c0 = ct * 32, yx0 = yt * 32;
    #pragma unroll
    for (int cy = r0; cy < 32; cy += 8)
        t[cy][x] = P[((size_t)(p * 128 + c0 + cy)) * 4096 + yx0 + x];
    __syncthreads();
    #pragma unroll
    for (int yy = r0; yy < 32; yy += 8)
        out[((size_t)(p * 4096 + yx0 + yy)) * 128 + c0 + x] = t[x][yy];
}

// ---------------------------------------------------------------------------
// Combined weight prep (single launch)
// ---------------------------------------------------------------------------
#define PREP_N1 (512 * K1P)
#define PREP_N2 (512 * HID)
__global__ void prep_all_kernel(const float* __restrict__ W1, const float* __restrict__ W2,
                                const float* __restrict__ W3,
                                __nv_bfloat16* __restrict__ w1h, __nv_bfloat16* __restrict__ w1l,
                                __nv_bfloat16* __restrict__ w2h, __nv_bfloat16* __restrict__ w2l,
                                __nv_bfloat16* __restrict__ w3h, __nv_bfloat16* __restrict__ w3l) {
    int i = blockIdx.x * blockDim.x + threadIdx.x;
    const float* W; __nv_bfloat16 *oh, *ol; int Kin, Kpad, j;
    if (i < PREP_N1) {
        W = W1; oh = w1h; ol = w1l; Kin = 131; Kpad = K1P; j = i;
    } else if (i < PREP_N1 + PREP_N2) {
        W = W2; oh = w2h; ol = w2l; Kin = 512; Kpad = HID; j = i - PREP_N1;
    } else if (i < PREP_N1 + 2 * PREP_N2) {
        W = W3; oh = w3h; ol = w3l; Kin = 512; Kpad = HID; j = i - PREP_N1 - PREP_N2;
    } else return;
    int n = j / Kpad, k = j % Kpad;
    float x = (k < Kin) ? W[(size_t)k * 512 + n] : 0.0f;
    __nv_bfloat16 h, l;
    split_bf16(x, h, l);
    oh[j] = h; ol[j] = l;
}

// ---------------------------------------------------------------------------
// Sampler: warp per query; channel-last planes -> coalesced float4 corner loads.
// ---------------------------------------------------------------------------
__global__ __launch_bounds__(256)
void sampler_kernel(const float* __restrict__ PT, const float* __restrict__ query,
                    __nv_bfloat16* __restrict__ h0h, __nv_bfloat16* __restrict__ h0l) {
    int n = blockIdx.x * 8 + (threadIdx.x >> 5);
    int lane = threadIdx.x & 31;

    float q0 = __ldg(query + 3 * n + 0);
    float q1 = __ldg(query + 3 * n + 1);
    float q2 = __ldg(query + 3 * n + 2);

    float u[3] = { q0 / 1.1f, q1 / 1.1f, q0 / 1.1f };
    float v[3] = { q2 / 1.1f, q2 / 1.1f, q1 / 1.1f };

    float4 acc = make_float4(0.f, 0.f, 0.f, 0.f);

    #pragma unroll
    for (int p = 0; p < 3; ++p) {
        float x = (u[p] + 1.0f) * 0.5f * 63.0f;
        float y = (v[p] + 1.0f) * 0.5f * 63.0f;
        float x0f = floorf(x), y0f = floorf(y);
        float wx = x - x0f, wy = y - y0f;
        int x0 = min(max((int)x0f, 0), 63);
        int y0 = min(max((int)y0f, 0), 63);
        int x1 = min(x0 + 1, 63);
        int y1 = min(y0 + 1, 63);
        float w00 = (1.f - wx) * (1.f - wy);
        float w01 = wx * (1.f - wy);
        float w10 = (1.f - wx) * wy;
        float w11 = wx * wy;
        const float* base = PT + (size_t)p * 4096 * 128 + lane * 4;
        float4 v00 = *(const float4*)(base + (size_t)(y0 * 64 + x0) * 128);
        float4 v01 = *(const float4*)(base + (size_t)(y0 * 64 + x1) * 128);
        float4 v10 = *(const float4*)(base + (size_t)(y1 * 64 + x0) * 128);
        float4 v11 = *(const float4*)(base + (size_t)(y1 * 64 + x1) * 128);
        acc.x += w00 * v00.x + w01 * v01.x + w10 * v10.x + w11 * v11.x;
        acc.y += w00 * v00.y + w01 * v01.y + w10 * v10.y + w11 * v11.y;
        acc.z += w00 * v00.z + w01 * v01.z + w10 * v10.z + w11 * v11.z;
        acc.w += w00 * v00.w + w01 * v01.w + w10 * v10.w + w11 * v11.w;
    }

    __nv_bfloat16 hv[4], lv[4];
    split_bf16(acc.x, hv[0], lv[0]);
    split_bf16(acc.y, hv[1], lv[1]);
    split_bf16(acc.z, hv[2], lv[2]);
    split_bf16(acc.w, hv[3], lv[3]);
    size_t rb = (size_t)n * K1P;
    *(uint2*)(h0h + rb + lane * 4) = *(uint2*)hv;
    *(uint2*)(h0l + rb + lane * 4) = *(uint2*)lv;

    {
        int col = 128 + lane;
        float val = (lane == 0) ? q0 : (lane == 1) ? q1 : (lane == 2) ? q2 : 0.0f;
        __nv_bfloat16 h, l;
        split_bf16(val, h, l);
        h0h[rb + col] = h;
        h0l[rb + col] = l;
    }
}

// ---------------------------------------------------------------------------
// bf16 HMMA GEMM: C[M x 512] = relu(A[M x K] @ B^T + bias)
//   3-term compensated: AhBh + AhBl + AlBh, fp32 accum.
//   CTA 128x128, BK=32, 8 warps, 3-stage cp.async pipeline.
//   64B smem rows + XOR chunk swizzle -> 32KB/stage, 96KB total -> 2 CTAs/SM.
// ---------------------------------------------------------------------------
#define MAT_BYTES   (128 * 64)          // 8192
#define STAGE_BYTES (4 * MAT_BYTES)     // 32768
#define GSMEM       (3 * STAGE_BYTES)   // 98304

template<int K, bool FINAL>
__global__ __launch_bounds__(256, 2)
void gemm_kernel(const __nv_bfloat16* __restrict__ Ah, const __nv_bfloat16* __restrict__ Al,
                 const __nv_bfloat16* __restrict__ Bh, const __nv_bfloat16* __restrict__ Bl,
                 const float* __restrict__ bias,
                 __nv_bfloat16* __restrict__ Ch, __nv_bfloat16* __restrict__ Cl,
                 const float* __restrict__ Wo, float* __restrict__ part) {
    extern __shared__ char smem[];
    const int tid  = threadIdx.x;
    const int lane = tid & 31, wid = tid >> 5;
    const int m0 = blockIdx.y * 128;
    const int n0 = blockIdx.x * 128;
    const uint32_t sb = smem_u32(smem);

    const int lr0 = tid >> 2;       // load row 0..63
    const int lc0 = tid & 3;        // logical 16B chunk

    float acc[2][8][4];
    #pragma unroll
    for (int a = 0; a < 2; ++a)
        #pragma unroll
        for (int b = 0; b < 8; ++b)
            #pragma unroll
            for (int c = 0; c < 4; ++c) acc[a][b][c] = 0.0f;

    auto load_stage = [&](int buf, int kt) {
        uint32_t s = sb + buf * STAGE_BYTES;
        #pragma unroll
        for (int rep = 0; rep < 2; ++rep) {
            int r = lr0 + rep * 64;
            uint32_t so = swz((uint32_t)r, (uint32_t)lc0);
            size_t ga = (size_t)(m0 + r) * K + kt + lc0 * 8;
            size_t gb = (size_t)(n0 + r) * K + kt + lc0 * 8;
            cp16(s + so,                 Ah + ga);
            cp16(s + MAT_BYTES + so,     Al + ga);
            cp16(s + 2 * MAT_BYTES + so, Bh + gb);
            cp16(s + 3 * MAT_BYTES + so, Bl + gb);
        }
        cp_commit();
    };

    constexpr int NS = K / 32;
    load_stage(0, 0);
    load_stage(1, 32);

    const int g = lane >> 3, t = lane & 7;
    const int warp_m = wid & 3, warp_n = wid >> 2;
    const uint32_t a_row  = warp_m * 32 + ((g & 1) << 3) + t;
    const uint32_t a_coff = (uint32_t)(g >> 1);
    const uint32_t b_row  = warp_n * 64 + ((g >> 1) << 3) + t;
    const uint32_t b_coff = (uint32_t)(g & 1);

    int buf = 0;
    for (int st = 0; st < NS; ++st) {
        if (st + 1 < NS) cp_wait<1>(); else cp_wait<0>();
        __syncthreads();

        if (st + 2 < NS) {
            int nb3 = buf + 2; if (nb3 >= 3) nb3 -= 3;
            load_stage(nb3, (st + 2) * 32);
        }

        uint32_t s = sb + buf * STAGE_BYTES;
        #pragma unroll
        for (int ks = 0; ks < 2; ++ks) {
            uint32_t aH[2][4], aL[2][4];
            #pragma unroll
            for (int mt = 0; mt < 2; ++mt) {
                uint32_t ad = s + swz(a_row + mt * 16, (uint32_t)(ks * 2) + a_coff);
                ldsm4(aH[mt][0], aH[mt][1], aH[mt][2], aH[mt][3], ad);
                ldsm4(aL[mt][0], aL[mt][1], aL[mt][2], aL[mt][3], ad + MAT_BYTES);
            }
            #pragma unroll
            for (int nbp = 0; nbp < 4; ++nbp) {
                uint32_t bH[2][2], bL[2][2];
                uint32_t bd = s + 2 * MAT_BYTES + swz(b_row + nbp * 16, (uint32_t)(ks * 2) + b_coff);
                ldsm4(bH[0][0], bH[0][1], bH[1][0], bH[1][1], bd);
                ldsm4(bL[0][0], bL[0][1], bL[1][0], bL[1][1], bd + MAT_BYTES);
                #pragma unroll
                for (int mt = 0; mt < 2; ++mt)
                    #pragma unroll
                    for (int h = 0; h < 2; ++h) {
                        mma16816(acc[mt][2 * nbp + h], aH[mt], bH[h]);
                        mma16816(acc[mt][2 * nbp + h], aH[mt], bL[h]);
                        mma16816(acc[mt][2 * nbp + h], aL[mt], bH[h]);
                    }
            }
        }
        if (++buf == 3) buf = 0;
    }

    // ---------------- epilogue ----------------
    const int row_l = lane >> 2;
    const int colq  = (lane & 3) * 2;

    #pragma unroll
    for (int mt = 0; mt < 2; ++mt) {
        int r0g = m0 + warp_m * 32 + mt * 16 + row_l;
        if (!FINAL) {
            #pragma unroll
            for (int nb = 0; nb < 8; ++nb) {
                int c0 = n0 + warp_n * 64 + nb * 8 + colq;
                float b0 = __ldg(bias + c0), b1 = __ldg(bias + c0 + 1);
                float v0 = fmaxf(acc[mt][nb][0] + b0, 0.f);
                float v1 = fmaxf(acc[mt][nb][1] + b1, 0.f);
                float v2 = fmaxf(acc[mt][nb][2] + b0, 0.f);
                float v3 = fmaxf(acc[mt][nb][3] + b1, 0.f);
                __nv_bfloat16 h0v, l0v, h1v, l1v;
                split_bf16(v0, h0v, l0v); split_bf16(v1, h1v, l1v);
                *(uint32_t*)(Ch + (size_t)r0g * HID + c0) = pack_bf2(h0v, h1v);
                *(uint32_t*)(Cl + (size_t)r0g * HID + c0) = pack_bf2(l0v, l1v);
                split_bf16(v2, h0v, l0v); split_bf16(v3, h1v, l1v);
                *(uint32_t*)(Ch + (size_t)(r0g + 8) * HID + c0) = pack_bf2(h0v, h1v);
                *(uint32_t*)(Cl + (size_t)(r0g + 8) * HID + c0) = pack_bf2(l0v, l1v);
            }
        } else {
            float p0 = 0.f, p1 = 0.f;
            #pragma unroll
            for (int nb = 0; nb < 8; ++nb) {
                int c0 = n0 + warp_n * 64 + nb * 8 + colq;
                float b0 = __ldg(bias + c0), b1 = __ldg(bias + c0 + 1);
                float w0 = __ldg(Wo + c0),   w1 = __ldg(Wo + c0 + 1);
                p0 += fmaxf(acc[mt][nb][0] + b0, 0.f) * w0
                    + fmaxf(acc[mt][nb][1] + b1, 0.f) * w1;
                p1 += fmaxf(acc[mt][nb][2] + b0, 0.f) * w0
                    + fmaxf(acc[mt][nb][3] + b1, 0.f) * w1;
            }
            p0 += __shfl_xor_sync(0xFFFFFFFFu, p0, 1);
            p0 += __shfl_xor_sync(0xFFFFFFFFu, p0, 2);
            p1 += __shfl_xor_sync(0xFFFFFFFFu, p1, 1);
            p1 += __shfl_xor_sync(0xFFFFFFFFu, p1, 2);
            __shared__ float red[128];
            if ((lane & 3) == 0) {
                int mi = warp_m * 32 + mt * 16 + row_l;
                if (warp_n == 0) { red[mi] = p0; red[mi + 8] = p1; }
            }
            __syncthreads();
            if ((lane & 3) == 0 && warp_n == 1) {
                int mi = warp_m * 32 + mt * 16 + row_l;
                part[(size_t)blockIdx.x * NQ + m0 + mi]     = red[mi] + p0;
                part[(size_t)blockIdx.x * NQ + m0 + mi + 8] = red[mi + 8] + p1;
            }
            __syncthreads();
        }
    }
}

// ---------------------------------------------------------------------------
// final: out = tanh(sum of 4 slabs + bo)
// ---------------------------------------------------------------------------
__global__ void tanh_kernel(const float* __restrict__ part, const float* __restrict__ bo,
                            float* __restrict__ out) {
    int i = blockIdx.x * blockDim.x + threadIdx.x;
    if (i < NQ) {
        float s = part[i] + part[NQ + (size_t)i] + part[2 * (size_t)NQ + i] + part[3 * (size_t)NQ + i];
        out[i] = tanhf(s + __ldg(bo));
    }
}

// ---------------------------------------------------------------------------
// Launcher
// ---------------------------------------------------------------------------
extern "C" void kernel_launch(void* const* d_in, const int* in_sizes, int n_in,
                              void* d_out, int out_size) {
    const float* planes = (const float*)d_in[0];
    const float* query  = (const float*)d_in[1];
    const float* W1     = (const float*)d_in[2];
    const float* b1     = (const float*)d_in[3];
    const float* W2     = (const float*)d_in[4];
    const float* b2     = (const float*)d_in[5];
    const float* W3     = (const float*)d_in[6];
    const float* b3     = (const float*)d_in[7];
    const float* Wo     = (const float*)d_in[8];
    const float* bo     = (const float*)d_in[9];
    float* out = (float*)d_out;

    float *planesT, *part;
    __nv_bfloat16 *h0h, *h0l, *w1h, *w1l, *w2h, *w2l, *w3h, *w3l, *ah, *al, *bh, *bl;
    cudaGetSymbolAddress((void**)&planesT, g_planesT);
    cudaGetSymbolAddress((void**)&part, g_part);
    cudaGetSymbolAddress((void**)&h0h, g_h0h);
    cudaGetSymbolAddress((void**)&h0l, g_h0l);
    cudaGetSymbolAddress((void**)&w1h, g_w1h);
    cudaGetSymbolAddress((void**)&w1l, g_w1l);
    cudaGetSymbolAddress((void**)&w2h, g_w2h);
    cudaGetSymbolAddress((void**)&w2l, g_w2l);
    cudaGetSymbolAddress((void**)&w3h, g_w3h);
    cudaGetSymbolAddress((void**)&w3l, g_w3l);
    cudaGetSymbolAddress((void**)&ah, g_ah);
    cudaGetSymbolAddress((void**)&al, g_al);
    cudaGetSymbolAddress((void**)&bh, g_bh);
    cudaGetSymbolAddress((void**)&bl, g_bl);

    cudaFuncSetAttribute(gemm_kernel<K1P, false>,
                         cudaFuncAttributeMaxDynamicSharedMemorySize, GSMEM);
    cudaFuncSetAttribute(gemm_kernel<HID, false>,
                         cudaFuncAttributeMaxDynamicSharedMemorySize, GSMEM);
    cudaFuncSetAttribute(gemm_kernel<HID, true>,
                         cudaFuncAttributeMaxDynamicSharedMemorySize, GSMEM);

    // launch order chosen so launch #5 (1-indexed) = layer-2 GEMM for ncu -s 5
    tplanes_kernel<<<3 * 128 * 4, 256>>>(planes, planesT);                       // 1

    int prep_total = PREP_N1 + 2 * PREP_N2;
    prep_all_kernel<<<(prep_total + 255) / 256, 256>>>(W1, W2, W3,               // 2
                                                       w1h, w1l, w2h, w2l, w3h, w3l);

    sampler_kernel<<<NQ / 8, 256>>>(planesT, query, h0h, h0l);                   // 3

    dim3 grid(4, NQ / 128);
    gemm_kernel<K1P, false><<<grid, 256, GSMEM>>>(                               // 4
        h0h, h0l, w1h, w1l, b1, ah, al, nullptr, nullptr);
    gemm_kernel<HID, false><<<grid, 256, GSMEM>>>(                               // 5  <- profiled
        ah, al, w2h, w2l, b2, bh, bl, nullptr, nullptr);
    gemm_kernel<HID, true><<<grid, 256, GSMEM>>>(                                // 6
        bh, bl, w3h, w3l, b3, nullptr, nullptr, Wo, part);

    tanh_kernel<<<NQ / 256, 256>>>(part, bo, out);                               // 7
}